// round 5
// baseline (speedup 1.0000x reference)
#include <cuda_runtime.h>

#define B_ 2
#define T_ 2048
#define D_ 1024
#define NH_ 16
#define NKV_ 4
#define HD_ 64
#define QKVD 1536
#define MTOK (B_*T_)
#define SP 68   // padded shared row (68*4=272B, 16B aligned)

// ---------------- scratch (static device allocations; no cudaMalloc) --------
__device__ float g_qkv[(size_t)MTOK * QKVD];            // 25 MB
__device__ float g_q[(size_t)B_ * NH_ * T_ * HD_];      // 16.8 MB
__device__ float g_k[(size_t)B_ * NKV_ * T_ * HD_];     // 4.2 MB
__device__ float g_v[(size_t)B_ * NKV_ * T_ * HD_];     // 4.2 MB
__device__ float g_ao[(size_t)B_ * NH_ * T_ * HD_];     // 16.8 MB
__device__ float g_att[(size_t)MTOK * D_];              // 16.8 MB

// ---------------- generic NT SGEMM: C[M,N] = A[M,K] * B[N,K]^T ---------------
// BM=128, BN=64, BK=16, 256 threads, 8x4 accumulators per thread.
__global__ __launch_bounds__(256) void sgemm_nt(const float* __restrict__ A,
                                                const float* __restrict__ Bm,
                                                float* __restrict__ C,
                                                int M, int N, int K) {
    __shared__ float As[16][132];
    __shared__ float Bs[16][68];
    const int tid = threadIdx.x;
    const int tx = tid & 15, ty = tid >> 4;
    const int m0 = blockIdx.y * 128, n0 = blockIdx.x * 64;

    float acc[8][4];
#pragma unroll
    for (int i = 0; i < 8; i++)
#pragma unroll
        for (int j = 0; j < 4; j++) acc[i][j] = 0.f;

    for (int k0 = 0; k0 < K; k0 += 16) {
#pragma unroll
        for (int it = 0; it < 2; ++it) {          // A tile 128x16
            int lin = tid + it * 256;
            int m = lin >> 2, kq = (lin & 3) * 4;
            float4 av = *(const float4*)(A + (size_t)(m0 + m) * K + k0 + kq);
            As[kq + 0][m] = av.x; As[kq + 1][m] = av.y;
            As[kq + 2][m] = av.z; As[kq + 3][m] = av.w;
        }
        {                                          // B tile 64x16
            int m = tid >> 2, kq = (tid & 3) * 4;
            float4 bv = *(const float4*)(Bm + (size_t)(n0 + m) * K + k0 + kq);
            Bs[kq + 0][m] = bv.x; Bs[kq + 1][m] = bv.y;
            Bs[kq + 2][m] = bv.z; Bs[kq + 3][m] = bv.w;
        }
        __syncthreads();
#pragma unroll
        for (int kk = 0; kk < 16; ++kk) {
            float4 a0 = *(const float4*)&As[kk][ty * 8];
            float4 a1 = *(const float4*)&As[kk][ty * 8 + 4];
            float4 b  = *(const float4*)&Bs[kk][tx * 4];
            float ar[8] = {a0.x, a0.y, a0.z, a0.w, a1.x, a1.y, a1.z, a1.w};
            float br[4] = {b.x, b.y, b.z, b.w};
#pragma unroll
            for (int i = 0; i < 8; i++)
#pragma unroll
                for (int j = 0; j < 4; j++) acc[i][j] += ar[i] * br[j];
        }
        __syncthreads();
    }
#pragma unroll
    for (int i = 0; i < 8; i++) {
        float4 o = {acc[i][0], acc[i][1], acc[i][2], acc[i][3]};
        *(float4*)(C + (size_t)(m0 + ty * 8 + i) * N + n0 + tx * 4) = o;
    }
}

// ---------------- RoPE + per-head scale + layout split -----------------------
// qkv layout: [(b,t), slot*64+d] with 24 slots (16 q, 4 k, 4 v).
__global__ __launch_bounds__(256) void rope_kernel(const float* __restrict__ cosp,
                                                   const float* __restrict__ sinp,
                                                   const float* __restrict__ q_scale,
                                                   const float* __restrict__ k_scale) {
    int gtid = blockIdx.x * 256 + threadIdx.x;
    int row = gtid >> 6;
    int d = gtid & 63;
    int b = row / (T_ * 24);
    int rem = row % (T_ * 24);
    int t = rem / 24, slot = rem % 24;
    const float* src = g_qkv + (size_t)row * 64;
    float val = src[d];
    if (slot < 20) {
        float scale = (slot < 16) ? q_scale[slot] : k_scale[slot - 16];
        float out;
        if (d < 16) {
            int p = d & 7;
            float c = cosp[t * 8 + p], s = sinp[t * 8 + p];
            if (d < 8) {
                float x1 = val * scale, x2 = src[d + 8] * scale;
                out = x1 * c - x2 * s;
            } else {
                float x1 = src[d - 8] * scale, x2 = val * scale;
                out = x1 * s + x2 * c;
            }
        } else {
            out = val * scale;
        }
        if (slot < 16)
            g_q[(((size_t)(b * NH_ + slot)) * T_ + t) * 64 + d] = out;
        else
            g_k[(((size_t)(b * NKV_ + slot - 16)) * T_ + t) * 64 + d] = out;
    } else {
        g_v[(((size_t)(b * NKV_ + slot - 20)) * T_ + t) * 64 + d] = val;
    }
}

// ---------------- causal flash attention (fp32), GQA -------------------------
// grid (T/64, NH, B), 256 threads = 16x16, each thread 4x4 of S/O.
__global__ __launch_bounds__(256) void flash_kernel() {
    extern __shared__ float smem[];
    float* Qst = smem;                 // [dim][qrow]  64 x SP
    float* KPs = smem + 64 * SP;       // Kst [dim][kvcol] then Pst [kvcol][qrow]
    float* Vs  = smem + 2 * 64 * SP;   // [kvrow][dim]

    const int b = blockIdx.z, h = blockIdx.y;
    const int q0 = blockIdx.x * 64;
    const int tid = threadIdx.x, tx = tid & 15, ty = tid >> 4;

    const float* Qb = g_q + ((size_t)(b * NH_ + h) * T_ + q0) * 64;
    const float* Kb = g_k + ((size_t)(b * NKV_ + (h >> 2)) * T_) * 64;
    const float* Vb = g_v + ((size_t)(b * NKV_ + (h >> 2)) * T_) * 64;

#pragma unroll
    for (int it = 0; it < 4; ++it) {      // Q tile transposed into smem
        int lin = tid + it * 256;
        int r = lin >> 4, dq = (lin & 15) * 4;
        float4 qv = *(const float4*)(Qb + r * 64 + dq);
        Qst[(dq + 0) * SP + r] = qv.x; Qst[(dq + 1) * SP + r] = qv.y;
        Qst[(dq + 2) * SP + r] = qv.z; Qst[(dq + 3) * SP + r] = qv.w;
    }

    float m[4], l[4], O[4][4];
#pragma unroll
    for (int i = 0; i < 4; i++) {
        m[i] = -1e30f; l[i] = 0.f;
#pragma unroll
        for (int j = 0; j < 4; j++) O[i][j] = 0.f;
    }

    for (int j0 = 0; j0 <= q0; j0 += 64) {
        __syncthreads();   // protects Qst (1st iter) and KPs/Vs reuse
#pragma unroll
        for (int it = 0; it < 4; ++it) {
            int lin = tid + it * 256;
            int r = lin >> 4, dq = (lin & 15) * 4;
            float4 kv = *(const float4*)(Kb + (size_t)(j0 + r) * 64 + dq);
            KPs[(dq + 0) * SP + r] = kv.x; KPs[(dq + 1) * SP + r] = kv.y;
            KPs[(dq + 2) * SP + r] = kv.z; KPs[(dq + 3) * SP + r] = kv.w;
            float4 vv = *(const float4*)(Vb + (size_t)(j0 + r) * 64 + dq);
            *(float4*)&Vs[r * SP + dq] = vv;
        }
        __syncthreads();

        float s[4][4];
#pragma unroll
        for (int i = 0; i < 4; i++)
#pragma unroll
            for (int j = 0; j < 4; j++) s[i][j] = 0.f;

#pragma unroll 8
        for (int kk = 0; kk < 64; ++kk) {
            float4 qa  = *(const float4*)&Qst[kk * SP + ty * 4];
            float4 kbv = *(const float4*)&KPs[kk * SP + tx * 4];
            float ar[4] = {qa.x, qa.y, qa.z, qa.w};
            float br[4] = {kbv.x, kbv.y, kbv.z, kbv.w};
#pragma unroll
            for (int i = 0; i < 4; i++)
#pragma unroll
                for (int j = 0; j < 4; j++) s[i][j] += ar[i] * br[j];
        }

        const bool diag = (j0 == q0);
#pragma unroll
        for (int i = 0; i < 4; i++)
#pragma unroll
            for (int j = 0; j < 4; j++) {
                s[i][j] *= 0.125f;  // HD^-0.5
                if (diag && (j0 + tx * 4 + j > q0 + ty * 4 + i)) s[i][j] = -1e30f;
            }

        float p[4][4];
#pragma unroll
        for (int i = 0; i < 4; i++) {
            float rmax = fmaxf(fmaxf(s[i][0], s[i][1]), fmaxf(s[i][2], s[i][3]));
#pragma unroll
            for (int o = 1; o < 16; o <<= 1)
                rmax = fmaxf(rmax, __shfl_xor_sync(0xffffffffu, rmax, o));
            float mn = fmaxf(m[i], rmax);
            float rs = 0.f;
#pragma unroll
            for (int j = 0; j < 4; j++) { p[i][j] = __expf(s[i][j] - mn); rs += p[i][j]; }
#pragma unroll
            for (int o = 1; o < 16; o <<= 1)
                rs += __shfl_xor_sync(0xffffffffu, rs, o);
            float sc = __expf(m[i] - mn);
            l[i] = l[i] * sc + rs;
            m[i] = mn;
#pragma unroll
            for (int j = 0; j < 4; j++) O[i][j] *= sc;
        }

        __syncthreads();   // everyone done reading Kst before Pst overwrite
#pragma unroll
        for (int j = 0; j < 4; j++)
#pragma unroll
            for (int i = 0; i < 4; i++)
                KPs[(tx * 4 + j) * SP + ty * 4 + i] = p[i][j];
        __syncthreads();

#pragma unroll 8
        for (int kk = 0; kk < 64; ++kk) {
            float4 pa = *(const float4*)&KPs[kk * SP + ty * 4];
            float4 vb = *(const float4*)&Vs[kk * SP + tx * 4];
            float ar[4] = {pa.x, pa.y, pa.z, pa.w};
            float br[4] = {vb.x, vb.y, vb.z, vb.w};
#pragma unroll
            for (int i = 0; i < 4; i++)
#pragma unroll
                for (int j = 0; j < 4; j++) O[i][j] += ar[i] * br[j];
        }
    }

    float* Ob = g_ao + ((size_t)(b * NH_ + h) * T_ + q0) * 64;
#pragma unroll
    for (int i = 0; i < 4; i++) {
        float inv = 1.f / l[i];
        float4 o = {O[i][0] * inv, O[i][1] * inv, O[i][2] * inv, O[i][3] * inv};
        *(float4*)(Ob + (ty * 4 + i) * 64 + tx * 4) = o;
    }
}

// ---------------- project-out-V epilogue: ao -= (ao.v / max(v.v,eps)) v -----
// one warp per (b,h,t); writes to (B,T,D) layout for the output GEMM.
__global__ __launch_bounds__(256) void epilogue_kernel() {
    int w = blockIdx.x * 8 + (threadIdx.x >> 5);
    int lane = threadIdx.x & 31;
    int b = w >> 15;            // / (NH*T) = 32768
    int h = (w >> 11) & 15;     // / T = 2048
    int t = w & 2047;
    const float* ao = g_ao + ((size_t)(b * NH_ + h) * T_ + t) * 64;
    const float* v  = g_v  + ((size_t)(b * NKV_ + (h >> 2)) * T_ + t) * 64;
    float a0 = ao[lane], a1 = ao[lane + 32];
    float v0 = v[lane],  v1 = v[lane + 32];
    float dot = a0 * v0 + a1 * v1;
    float nrm = v0 * v0 + v1 * v1;
#pragma unroll
    for (int o = 1; o < 32; o <<= 1) {
        dot += __shfl_xor_sync(0xffffffffu, dot, o);
        nrm += __shfl_xor_sync(0xffffffffu, nrm, o);
    }
    float f = dot / fmaxf(nrm, 1e-8f);
    float* outp = g_att + ((size_t)(b * T_ + t)) * D_ + h * 64;
    outp[lane]      = a0 - f * v0;
    outp[lane + 32] = a1 - f * v1;
}

// ---------------- launch -----------------------------------------------------
extern "C" void kernel_launch(void* const* d_in, const int* in_sizes, int n_in,
                              void* d_out, int out_size) {
    const float* x      = (const float*)d_in[0];
    const float* cosp   = (const float*)d_in[1];
    const float* sinp   = (const float*)d_in[2];
    // d_in[3]: attn_mask (tril) — causal structure is hardcoded
    const float* w_qkv  = (const float*)d_in[4];
    const float* w_out  = (const float*)d_in[5];
    const float* q_s    = (const float*)d_in[6];
    const float* k_s    = (const float*)d_in[7];
    float* out = (float*)d_out;

    float *qkv, *att;
    cudaGetSymbolAddress((void**)&qkv, g_qkv);
    cudaGetSymbolAddress((void**)&att, g_att);

    // 1) QKV projection: [4096,1536] = x[4096,1024] @ w_qkv[1536,1024]^T
    sgemm_nt<<<dim3(QKVD / 64, MTOK / 128), 256>>>(x, w_qkv, qkv, MTOK, QKVD, D_);

    // 2) scales + RoPE + split into (b,h,t,d) layouts
    rope_kernel<<<(B_ * T_ * 24 * 64) / 256, 256>>>(cosp, sinp, q_s, k_s);

    // 3) causal flash attention
    int fa_smem = 3 * 64 * SP * (int)sizeof(float);   // 52224 B
    cudaFuncSetAttribute(flash_kernel, cudaFuncAttributeMaxDynamicSharedMemorySize, fa_smem);
    flash_kernel<<<dim3(T_ / 64, NH_, B_), 256, fa_smem>>>();

    // 4) project-out-V epilogue -> (B,T,D) layout
    epilogue_kernel<<<(B_ * NH_ * T_) / 8, 256>>>();

    // 5) output projection: out[4096,1024] = att @ w_out[1024,1024]^T
    sgemm_nt<<<dim3(D_ / 64, MTOK / 128), 256>>>(att, w_out, out, MTOK, D_, D_);
}

// round 6
// speedup vs baseline: 2.0619x; 2.0619x over previous
#include <cuda_runtime.h>
#include <cstdint>

#define B_ 2
#define T_ 2048
#define D_ 1024
#define NH_ 16
#define NKV_ 4
#define HD_ 64
#define QKVD 1536
#define MTOK (B_*T_)
#define SP 68

// ---------------- scratch ----------------------------------------------------
__device__ float g_qkv[(size_t)MTOK * QKVD];
__device__ float g_q[(size_t)B_ * NH_ * T_ * HD_];
__device__ float g_k[(size_t)B_ * NKV_ * T_ * HD_];
__device__ float g_v[(size_t)B_ * NKV_ * T_ * HD_];
__device__ float g_ao[(size_t)B_ * NH_ * T_ * HD_];
__device__ float g_att[(size_t)MTOK * D_];

// ---------------- tf32 helpers ----------------------------------------------
__device__ __forceinline__ uint32_t tf32bits(float x) {
    uint32_t y;
    asm("cvt.rna.tf32.f32 %0, %1;" : "=r"(y) : "f"(x));
    return y;
}
__device__ __forceinline__ float tf32f(float x) {
    return __uint_as_float(tf32bits(x));
}
__device__ __forceinline__ void mma_tf32(float c[4],
                                         uint32_t a0, uint32_t a1, uint32_t a2, uint32_t a3,
                                         uint32_t b0, uint32_t b1) {
    asm volatile(
        "mma.sync.aligned.m16n8k8.row.col.f32.tf32.tf32.f32 "
        "{%0,%1,%2,%3}, {%4,%5,%6,%7}, {%8,%9}, {%0,%1,%2,%3};"
        : "+f"(c[0]), "+f"(c[1]), "+f"(c[2]), "+f"(c[3])
        : "r"(a0), "r"(a1), "r"(a2), "r"(a3), "r"(b0), "r"(b1));
}

// ---------------- tf32 NT GEMM: C[M,N] = A[M,K] * B[N,K]^T -------------------
// BM=128 BN=64 BK=16, 8 warps (4x2), warp tile 32x32 = 2x4 m16n8k8 frags.
__global__ __launch_bounds__(256) void sgemm_tf32(const float* __restrict__ A,
                                                  const float* __restrict__ Bm,
                                                  float* __restrict__ C,
                                                  int M, int N, int K) {
    __shared__ float As[16][132];
    __shared__ float Bs[16][68];
    const int tid = threadIdx.x;
    const int lane = tid & 31, warp = tid >> 5;
    const int wm = warp & 3, wn = warp >> 2;
    const int m0 = blockIdx.y * 128, n0 = blockIdx.x * 64;
    const int rb = wm * 32, cb = wn * 32;
    const int lg = lane >> 2, lt = lane & 3;

    float acc[2][4][4];
#pragma unroll
    for (int i = 0; i < 2; i++)
#pragma unroll
        for (int j = 0; j < 4; j++)
#pragma unroll
            for (int e = 0; e < 4; e++) acc[i][j][e] = 0.f;

    for (int k0 = 0; k0 < K; k0 += 16) {
#pragma unroll
        for (int it = 0; it < 2; ++it) {           // A tile 128x16 (transposed)
            int lin = tid + it * 256;
            int m = lin >> 2, kq = (lin & 3) * 4;
            float4 av = *(const float4*)(A + (size_t)(m0 + m) * K + k0 + kq);
            As[kq + 0][m] = tf32f(av.x); As[kq + 1][m] = tf32f(av.y);
            As[kq + 2][m] = tf32f(av.z); As[kq + 3][m] = tf32f(av.w);
        }
        {                                           // B tile 64x16 (transposed)
            int m = tid >> 2, kq = (tid & 3) * 4;
            float4 bv = *(const float4*)(Bm + (size_t)(n0 + m) * K + k0 + kq);
            Bs[kq + 0][m] = tf32f(bv.x); Bs[kq + 1][m] = tf32f(bv.y);
            Bs[kq + 2][m] = tf32f(bv.z); Bs[kq + 3][m] = tf32f(bv.w);
        }
        __syncthreads();
#pragma unroll
        for (int ks = 0; ks < 2; ++ks) {
            const int kk = ks * 8;
            uint32_t a[2][4];
#pragma unroll
            for (int mf = 0; mf < 2; ++mf) {
                int r = rb + mf * 16 + lg;
                a[mf][0] = __float_as_uint(As[kk + lt][r]);
                a[mf][1] = __float_as_uint(As[kk + lt][r + 8]);
                a[mf][2] = __float_as_uint(As[kk + 4 + lt][r]);
                a[mf][3] = __float_as_uint(As[kk + 4 + lt][r + 8]);
            }
            uint32_t b[4][2];
#pragma unroll
            for (int nf = 0; nf < 4; ++nf) {
                int c = cb + nf * 8 + lg;
                b[nf][0] = __float_as_uint(Bs[kk + lt][c]);
                b[nf][1] = __float_as_uint(Bs[kk + 4 + lt][c]);
            }
#pragma unroll
            for (int mf = 0; mf < 2; ++mf)
#pragma unroll
                for (int nf = 0; nf < 4; ++nf)
                    mma_tf32(acc[mf][nf], a[mf][0], a[mf][1], a[mf][2], a[mf][3],
                             b[nf][0], b[nf][1]);
        }
        __syncthreads();
    }
#pragma unroll
    for (int mf = 0; mf < 2; ++mf)
#pragma unroll
        for (int nf = 0; nf < 4; ++nf) {
            int r = m0 + rb + mf * 16 + lg;
            int c = n0 + cb + nf * 8 + 2 * lt;
            float2 v0 = {acc[mf][nf][0], acc[mf][nf][1]};
            float2 v1 = {acc[mf][nf][2], acc[mf][nf][3]};
            *(float2*)(C + (size_t)r * N + c) = v0;
            *(float2*)(C + (size_t)(r + 8) * N + c) = v1;
        }
}

// ---------------- RoPE + per-head scale + layout split (unchanged) -----------
__global__ __launch_bounds__(256) void rope_kernel(const float* __restrict__ cosp,
                                                   const float* __restrict__ sinp,
                                                   const float* __restrict__ q_scale,
                                                   const float* __restrict__ k_scale) {
    int gtid = blockIdx.x * 256 + threadIdx.x;
    int row = gtid >> 6;
    int d = gtid & 63;
    int b = row / (T_ * 24);
    int rem = row % (T_ * 24);
    int t = rem / 24, slot = rem % 24;
    const float* src = g_qkv + (size_t)row * 64;
    float val = src[d];
    if (slot < 20) {
        float scale = (slot < 16) ? q_scale[slot] : k_scale[slot - 16];
        float out;
        if (d < 16) {
            int p = d & 7;
            float c = cosp[t * 8 + p], s = sinp[t * 8 + p];
            if (d < 8) {
                float x1 = val * scale, x2 = src[d + 8] * scale;
                out = x1 * c - x2 * s;
            } else {
                float x1 = src[d - 8] * scale, x2 = val * scale;
                out = x1 * s + x2 * c;
            }
        } else {
            out = val * scale;
        }
        if (slot < 16)
            g_q[(((size_t)(b * NH_ + slot)) * T_ + t) * 64 + d] = out;
        else
            g_k[(((size_t)(b * NKV_ + slot - 16)) * T_ + t) * 64 + d] = out;
    } else {
        g_v[(((size_t)(b * NKV_ + slot - 20)) * T_ + t) * 64 + d] = val;
    }
}

// ---------------- tf32 causal flash attention --------------------------------
// grid (T/128, NH, B), 8 warps; warp w owns q rows [q0+16w, q0+16w+16).
__global__ __launch_bounds__(256, 1) void flash_tf32() {
    extern __shared__ float smem[];
    float* Ks = smem;                         // [kv 64][d SP]
    float* Vt = smem + 64 * SP;               // [d 64][kv SP]
    const int tid = threadIdx.x;
    const int lane = tid & 31, warp = tid >> 5;
    float* Ps = smem + 2 * 64 * SP + warp * 16 * SP;  // per-warp [16][SP]

    const int b = blockIdx.z, h = blockIdx.y;
    const int q0 = blockIdx.x * 128;
    const int qr0 = q0 + warp * 16;
    const int lg = lane >> 2, lt = lane & 3;

    const float* Qb = g_q + ((size_t)(b * NH_ + h) * T_) * 64;
    const float* Kb = g_k + ((size_t)(b * NKV_ + (h >> 2)) * T_) * 64;
    const float* Vb = g_v + ((size_t)(b * NKV_ + (h >> 2)) * T_) * 64;

    // Q fragments (pre-scaled by HD^-0.5, tf32-rounded), held in registers.
    uint32_t qf[8][4];
    {
        int r = qr0 + lg;
#pragma unroll
        for (int kf = 0; kf < 8; ++kf) {
            qf[kf][0] = tf32bits(Qb[(size_t)r * 64 + kf * 8 + lt] * 0.125f);
            qf[kf][1] = tf32bits(Qb[(size_t)(r + 8) * 64 + kf * 8 + lt] * 0.125f);
            qf[kf][2] = tf32bits(Qb[(size_t)r * 64 + kf * 8 + 4 + lt] * 0.125f);
            qf[kf][3] = tf32bits(Qb[(size_t)(r + 8) * 64 + kf * 8 + 4 + lt] * 0.125f);
        }
    }

    float m0r = -1e30f, m1r = -1e30f, l0 = 0.f, l1 = 0.f;
    float o[8][4];
#pragma unroll
    for (int nf = 0; nf < 8; ++nf)
#pragma unroll
        for (int e = 0; e < 4; ++e) o[nf][e] = 0.f;

    for (int j0 = 0; j0 <= q0 + 64; j0 += 64) {
        __syncthreads();
#pragma unroll
        for (int it = 0; it < 4; ++it) {       // K row-major, V transposed
            int lin = tid + it * 256;
            int r = lin >> 4, dq = (lin & 15) * 4;
            float4 k4 = *(const float4*)(Kb + (size_t)(j0 + r) * 64 + dq);
            float4 kc = {tf32f(k4.x), tf32f(k4.y), tf32f(k4.z), tf32f(k4.w)};
            *(float4*)&Ks[r * SP + dq] = kc;
            float4 v4 = *(const float4*)(Vb + (size_t)(j0 + r) * 64 + dq);
            Vt[(dq + 0) * SP + r] = tf32f(v4.x);
            Vt[(dq + 1) * SP + r] = tf32f(v4.y);
            Vt[(dq + 2) * SP + r] = tf32f(v4.z);
            Vt[(dq + 3) * SP + r] = tf32f(v4.w);
        }
        __syncthreads();

        if (j0 > qr0 + 15) continue;   // whole warp masked

        float s[8][4];
#pragma unroll
        for (int nf = 0; nf < 8; ++nf)
#pragma unroll
            for (int e = 0; e < 4; ++e) s[nf][e] = 0.f;

#pragma unroll
        for (int kf = 0; kf < 8; ++kf) {
#pragma unroll
            for (int nf = 0; nf < 8; ++nf) {
                uint32_t b0 = __float_as_uint(Ks[(nf * 8 + lg) * SP + kf * 8 + lt]);
                uint32_t b1 = __float_as_uint(Ks[(nf * 8 + lg) * SP + kf * 8 + 4 + lt]);
                mma_tf32(s[nf], qf[kf][0], qf[kf][1], qf[kf][2], qf[kf][3], b0, b1);
            }
        }

        if (j0 + 63 > qr0) {           // causal masking needed
#pragma unroll
            for (int nf = 0; nf < 8; ++nf) {
                int col = j0 + nf * 8 + 2 * lt;
                int row0 = qr0 + lg, row1 = row0 + 8;
                if (col > row0)     s[nf][0] = -1e30f;
                if (col + 1 > row0) s[nf][1] = -1e30f;
                if (col > row1)     s[nf][2] = -1e30f;
                if (col + 1 > row1) s[nf][3] = -1e30f;
            }
        }

        // online softmax, rows r (c0,c1) and r+8 (c2,c3)
        float mx0 = -1e30f, mx1 = -1e30f;
#pragma unroll
        for (int nf = 0; nf < 8; ++nf) {
            mx0 = fmaxf(mx0, fmaxf(s[nf][0], s[nf][1]));
            mx1 = fmaxf(mx1, fmaxf(s[nf][2], s[nf][3]));
        }
        mx0 = fmaxf(mx0, __shfl_xor_sync(0xffffffffu, mx0, 1));
        mx0 = fmaxf(mx0, __shfl_xor_sync(0xffffffffu, mx0, 2));
        mx1 = fmaxf(mx1, __shfl_xor_sync(0xffffffffu, mx1, 1));
        mx1 = fmaxf(mx1, __shfl_xor_sync(0xffffffffu, mx1, 2));
        float mn0 = fmaxf(m0r, mx0), mn1 = fmaxf(m1r, mx1);
        float sc0 = __expf(m0r - mn0), sc1 = __expf(m1r - mn1);
        m0r = mn0; m1r = mn1;
        float rs0 = 0.f, rs1 = 0.f;
#pragma unroll
        for (int nf = 0; nf < 8; ++nf) {
            s[nf][0] = __expf(s[nf][0] - mn0);
            s[nf][1] = __expf(s[nf][1] - mn0);
            s[nf][2] = __expf(s[nf][2] - mn1);
            s[nf][3] = __expf(s[nf][3] - mn1);
            rs0 += s[nf][0] + s[nf][1];
            rs1 += s[nf][2] + s[nf][3];
        }
        rs0 += __shfl_xor_sync(0xffffffffu, rs0, 1);
        rs0 += __shfl_xor_sync(0xffffffffu, rs0, 2);
        rs1 += __shfl_xor_sync(0xffffffffu, rs1, 1);
        rs1 += __shfl_xor_sync(0xffffffffu, rs1, 2);
        l0 = l0 * sc0 + rs0;
        l1 = l1 * sc1 + rs1;
#pragma unroll
        for (int nf = 0; nf < 8; ++nf) {
            o[nf][0] *= sc0; o[nf][1] *= sc0;
            o[nf][2] *= sc1; o[nf][3] *= sc1;
        }

        // P -> per-warp smem (tf32-rounded), then O += P @ V
#pragma unroll
        for (int nf = 0; nf < 8; ++nf) {
            int c = nf * 8 + 2 * lt;
            Ps[lg * SP + c]           = tf32f(s[nf][0]);
            Ps[lg * SP + c + 1]       = tf32f(s[nf][1]);
            Ps[(lg + 8) * SP + c]     = tf32f(s[nf][2]);
            Ps[(lg + 8) * SP + c + 1] = tf32f(s[nf][3]);
        }
        __syncwarp();

#pragma unroll
        for (int kf = 0; kf < 8; ++kf) {
            uint32_t a0 = __float_as_uint(Ps[lg * SP + kf * 8 + lt]);
            uint32_t a1 = __float_as_uint(Ps[(lg + 8) * SP + kf * 8 + lt]);
            uint32_t a2 = __float_as_uint(Ps[lg * SP + kf * 8 + 4 + lt]);
            uint32_t a3 = __float_as_uint(Ps[(lg + 8) * SP + kf * 8 + 4 + lt]);
#pragma unroll
            for (int nf = 0; nf < 8; ++nf) {
                uint32_t b0 = __float_as_uint(Vt[(nf * 8 + lg) * SP + kf * 8 + lt]);
                uint32_t b1 = __float_as_uint(Vt[(nf * 8 + lg) * SP + kf * 8 + 4 + lt]);
                mma_tf32(o[nf], a0, a1, a2, a3, b0, b1);
            }
        }
        __syncwarp();
    }

    float inv0 = 1.f / l0, inv1 = 1.f / l1;
    float* Ob = g_ao + ((size_t)(b * NH_ + h) * T_) * 64;
    int r = qr0 + lg;
#pragma unroll
    for (int nf = 0; nf < 8; ++nf) {
        int c = nf * 8 + 2 * lt;
        float2 v0 = {o[nf][0] * inv0, o[nf][1] * inv0};
        float2 v1 = {o[nf][2] * inv1, o[nf][3] * inv1};
        *(float2*)(Ob + (size_t)r * 64 + c) = v0;
        *(float2*)(Ob + (size_t)(r + 8) * 64 + c) = v1;
    }
}

// ---------------- project-out-V epilogue (unchanged) -------------------------
__global__ __launch_bounds__(256) void epilogue_kernel() {
    int w = blockIdx.x * 8 + (threadIdx.x >> 5);
    int lane = threadIdx.x & 31;
    int b = w >> 15;
    int h = (w >> 11) & 15;
    int t = w & 2047;
    const float* ao = g_ao + ((size_t)(b * NH_ + h) * T_ + t) * 64;
    const float* v  = g_v  + ((size_t)(b * NKV_ + (h >> 2)) * T_ + t) * 64;
    float a0 = ao[lane], a1 = ao[lane + 32];
    float v0 = v[lane],  v1 = v[lane + 32];
    float dot = a0 * v0 + a1 * v1;
    float nrm = v0 * v0 + v1 * v1;
#pragma unroll
    for (int o = 1; o < 32; o <<= 1) {
        dot += __shfl_xor_sync(0xffffffffu, dot, o);
        nrm += __shfl_xor_sync(0xffffffffu, nrm, o);
    }
    float f = dot / fmaxf(nrm, 1e-8f);
    float* outp = g_att + ((size_t)(b * T_ + t)) * D_ + h * 64;
    outp[lane]      = a0 - f * v0;
    outp[lane + 32] = a1 - f * v1;
}

// ---------------- launch -----------------------------------------------------
extern "C" void kernel_launch(void* const* d_in, const int* in_sizes, int n_in,
                              void* d_out, int out_size) {
    const float* x      = (const float*)d_in[0];
    const float* cosp   = (const float*)d_in[1];
    const float* sinp   = (const float*)d_in[2];
    const float* w_qkv  = (const float*)d_in[4];
    const float* w_out  = (const float*)d_in[5];
    const float* q_s    = (const float*)d_in[6];
    const float* k_s    = (const float*)d_in[7];
    float* out = (float*)d_out;

    float *qkv, *att;
    cudaGetSymbolAddress((void**)&qkv, g_qkv);
    cudaGetSymbolAddress((void**)&att, g_att);

    // 1) QKV projection (tf32 tensor cores)
    sgemm_tf32<<<dim3(QKVD / 64, MTOK / 128), 256>>>(x, w_qkv, qkv, MTOK, QKVD, D_);

    // 2) scales + RoPE + split
    rope_kernel<<<(B_ * T_ * 24 * 64) / 256, 256>>>(cosp, sinp, q_s, k_s);

    // 3) causal flash attention (tf32 tensor cores)
    int fa_smem = (2 * 64 * SP + 8 * 16 * SP) * (int)sizeof(float);  // 69632 B
    cudaFuncSetAttribute(flash_tf32, cudaFuncAttributeMaxDynamicSharedMemorySize, fa_smem);
    flash_tf32<<<dim3(T_ / 128, NH_, B_), 256, fa_smem>>>();

    // 4) project-out-V epilogue
    epilogue_kernel<<<(B_ * NH_ * T_) / 8, 256>>>();

    // 5) output projection (tf32 tensor cores)
    sgemm_tf32<<<dim3(D_ / 64, MTOK / 128), 256>>>(att, w_out, out, MTOK, D_, D_);
}